// round 1
// baseline (speedup 1.0000x reference)
#include <cuda_runtime.h>
#include <math.h>

#define HEAD 128
#define CEMB 64
#define BATCH 8
#define TLEN 4096

#define BM 64
#define BN 64
#define PADK 129   // row pitch (floats) for Qs/Ks — odd pitch to break bank patterns
#define PADP 68    // row pitch for P (multiple of 4 for float4 stores)

// Scratch for projected Q (pre-scaled), K, V. Static device globals (no allocs).
__device__ float g_q[(size_t)BATCH * TLEN * HEAD];
__device__ float g_k[(size_t)BATCH * TLEN * HEAD];
__device__ float g_v[(size_t)BATCH * TLEN * HEAD];

// ---------------------------------------------------------------------------
// Kernel 1: fused QKV projection.  grid = B*T/64 blocks, 128 threads.
// Each block: 64 rows of x (smem), all three W in smem; thread t owns column h=t.
// ---------------------------------------------------------------------------
#define PROJ_SMEM ((64 * 64 + 3 * 64 * 128) * sizeof(float))

__global__ __launch_bounds__(128) void proj_kernel(
    const float* __restrict__ x,
    const float* __restrict__ Wq,
    const float* __restrict__ Wk,
    const float* __restrict__ Wv)
{
    extern __shared__ float sm[];
    float* xs = sm;               // [64][64]
    float* wq = xs + 64 * 64;     // [64][128]
    float* wk = wq + 64 * 128;
    float* wv = wk + 64 * 128;

    const int tid  = threadIdx.x;
    const int row0 = blockIdx.x * 64;

    // load x tile (coalesced float4)
    for (int i = tid; i < 64 * 64 / 4; i += 128)
        ((float4*)xs)[i] = ((const float4*)(x + (size_t)row0 * CEMB))[i];
    // load weights
    for (int i = tid; i < 64 * 128 / 4; i += 128) {
        ((float4*)wq)[i] = ((const float4*)Wq)[i];
        ((float4*)wk)[i] = ((const float4*)Wk)[i];
        ((float4*)wv)[i] = ((const float4*)Wv)[i];
    }
    __syncthreads();

    const int h = tid;                       // 0..127
    const float qscale = rsqrtf((float)HEAD);

    for (int r = 0; r < 64; r++) {
        float aq = 0.f, ak = 0.f, av = 0.f;
        #pragma unroll 16
        for (int c = 0; c < CEMB; c++) {
            float xv = xs[r * 64 + c];       // broadcast
            aq += xv * wq[c * 128 + h];      // conflict-free (bank = h%32)
            ak += xv * wk[c * 128 + h];
            av += xv * wv[c * 128 + h];
        }
        size_t o = (size_t)(row0 + r) * HEAD + h;
        g_q[o] = aq * qscale;                // fold 1/sqrt(H) into Q
        g_k[o] = ak;
        g_v[o] = av;
    }
}

// ---------------------------------------------------------------------------
// Kernel 2: flash attention.  grid = (T/64, B), 256 threads.
// thread (ty = tid/16, tx = tid%16):
//   S micro-tile: rows 4ty..+4, cols 4tx..+4     (4x4)
//   O micro-tile: rows 4ty..+4, cols 8tx..+8     (4x8 regs)
// ---------------------------------------------------------------------------
#define ATTN_SMEM ((2 * 64 * PADK + 64 * 128 + 64 * PADP + 3 * 64) * sizeof(float))

__global__ __launch_bounds__(256, 1) void attn_kernel(float* __restrict__ out)
{
    extern __shared__ float sm[];
    float* Qs   = sm;                    // [64][PADK]
    float* Ks   = Qs + 64 * PADK;        // [64][PADK]
    float* Vs   = Ks + 64 * PADK;        // [64][128]
    float* Ps   = Vs + 64 * 128;         // [64][PADP]
    float* mrow = Ps + 64 * PADP;        // [64]
    float* lrow = mrow + 64;             // [64]
    float* srow = lrow + 64;             // [64] rescale factor per row

    const int tid = threadIdx.x;
    const int tx  = tid & 15;
    const int ty  = tid >> 4;
    const int b   = blockIdx.y;
    const int qt  = blockIdx.x;
    const int q0  = qt * BM;

    // ---- load Q tile (once) ----
    const float* qg = g_q + ((size_t)b * TLEN + q0) * HEAD;
    for (int i = tid; i < 64 * 32; i += 256) {     // 64*128/4 float4s
        int r = i >> 5, c4 = i & 31;
        float4 v = ((const float4*)(qg + r * HEAD))[c4];
        float* d = Qs + r * PADK + c4 * 4;
        d[0] = v.x; d[1] = v.y; d[2] = v.z; d[3] = v.w;
    }
    if (tid < 64) { mrow[tid] = -3.0e38f; lrow[tid] = 0.f; }

    float o[4][8];
    #pragma unroll
    for (int i = 0; i < 4; i++)
        #pragma unroll
        for (int j = 0; j < 8; j++) o[i][j] = 0.f;

    const int ntile = qt + 1;   // causal: only key tiles <= query tile
    for (int t = 0; t < ntile; t++) {
        __syncthreads();        // protect Ks/Vs/Ps from previous iteration readers
        const int k0 = t * BN;
        const float* kg = g_k + ((size_t)b * TLEN + k0) * HEAD;
        const float* vg = g_v + ((size_t)b * TLEN + k0) * HEAD;
        for (int i = tid; i < 64 * 32; i += 256) {
            int r = i >> 5, c4 = i & 31;
            float4 kv = ((const float4*)(kg + r * HEAD))[c4];
            float* d = Ks + r * PADK + c4 * 4;
            d[0] = kv.x; d[1] = kv.y; d[2] = kv.z; d[3] = kv.w;
            ((float4*)(Vs + r * 128))[c4] = ((const float4*)(vg + r * HEAD))[c4];
        }
        __syncthreads();

        // ---- S = Q K^T  (4x4 per thread) ----
        float s[4][4];
        #pragma unroll
        for (int i = 0; i < 4; i++)
            #pragma unroll
            for (int j = 0; j < 4; j++) s[i][j] = 0.f;

        #pragma unroll 4
        for (int c = 0; c < HEAD; c++) {
            float qr[4], kr[4];
            #pragma unroll
            for (int i = 0; i < 4; i++) qr[i] = Qs[(4 * ty + i) * PADK + c];
            #pragma unroll
            for (int j = 0; j < 4; j++) kr[j] = Ks[(4 * tx + j) * PADK + c];
            #pragma unroll
            for (int i = 0; i < 4; i++)
                #pragma unroll
                for (int j = 0; j < 4; j++) s[i][j] += qr[i] * kr[j];
        }

        // ---- write scores to Ps with causal mask on diagonal tile ----
        const bool diag = (t == qt);
        #pragma unroll
        for (int i = 0; i < 4; i++) {
            int r = 4 * ty + i;
            if (diag) {
                #pragma unroll
                for (int j = 0; j < 4; j++)
                    if (4 * tx + j > r) s[i][j] = -3.0e38f;
            }
            float4 w;
            w.x = s[i][0]; w.y = s[i][1]; w.z = s[i][2]; w.w = s[i][3];
            *(float4*)(Ps + r * PADP + 4 * tx) = w;
        }
        __syncthreads();

        // ---- online softmax: one thread per row ----
        if (tid < 64) {
            const int r = tid;
            float* pr = Ps + r * PADP;
            float mold = mrow[r];
            float mx = mold;
            #pragma unroll 8
            for (int j2 = 0; j2 < 64; j2++) mx = fmaxf(mx, pr[j2]);
            float sf = __expf(mold - mx);          // 0 on first tile (underflow)
            float sum = 0.f;
            #pragma unroll 4
            for (int j2 = 0; j2 < 64; j2++) {
                float p = __expf(pr[j2] - mx);     // masked -> exp(-huge) = 0
                pr[j2] = p;
                sum += p;
            }
            lrow[r] = lrow[r] * sf + sum;
            mrow[r] = mx;
            srow[r] = sf;
        }
        __syncthreads();

        // ---- rescale O, then O += P @ V  (4x8 per thread) ----
        #pragma unroll
        for (int i = 0; i < 4; i++) {
            float sf = srow[4 * ty + i];
            #pragma unroll
            for (int j = 0; j < 8; j++) o[i][j] *= sf;
        }
        #pragma unroll 2
        for (int s2 = 0; s2 < BN; s2++) {
            float p[4];
            #pragma unroll
            for (int i = 0; i < 4; i++) p[i] = Ps[(4 * ty + i) * PADP + s2];
            float4 va = *(const float4*)(Vs + s2 * 128 + 8 * tx);
            float4 vb = *(const float4*)(Vs + s2 * 128 + 8 * tx + 4);
            float v0[8] = {va.x, va.y, va.z, va.w, vb.x, vb.y, vb.z, vb.w};
            #pragma unroll
            for (int i = 0; i < 4; i++)
                #pragma unroll
                for (int j = 0; j < 8; j++) o[i][j] += p[i] * v0[j];
        }
    }

    // ---- epilogue: O / l ----
    float* og = out + ((size_t)b * TLEN + q0) * HEAD;
    #pragma unroll
    for (int i = 0; i < 4; i++) {
        int r = 4 * ty + i;
        float inv = 1.f / lrow[r];
        float4 a, c;
        a.x = o[i][0] * inv; a.y = o[i][1] * inv; a.z = o[i][2] * inv; a.w = o[i][3] * inv;
        c.x = o[i][4] * inv; c.y = o[i][5] * inv; c.z = o[i][6] * inv; c.w = o[i][7] * inv;
        *(float4*)(og + r * HEAD + 8 * tx)     = a;
        *(float4*)(og + r * HEAD + 8 * tx + 4) = c;
    }
}

// ---------------------------------------------------------------------------
extern "C" void kernel_launch(void* const* d_in, const int* in_sizes, int n_in,
                              void* d_out, int out_size)
{
    (void)in_sizes; (void)n_in; (void)out_size;
    const float* x  = (const float*)d_in[0];
    const float* Wq = (const float*)d_in[1];
    const float* Wk = (const float*)d_in[2];
    const float* Wv = (const float*)d_in[3];
    float* out = (float*)d_out;

    cudaFuncSetAttribute(proj_kernel, cudaFuncAttributeMaxDynamicSharedMemorySize,
                         (int)PROJ_SMEM);
    cudaFuncSetAttribute(attn_kernel, cudaFuncAttributeMaxDynamicSharedMemorySize,
                         (int)ATTN_SMEM);

    proj_kernel<<<(BATCH * TLEN) / 64, 128, PROJ_SMEM>>>(x, Wq, Wk, Wv);

    dim3 grid(TLEN / BM, BATCH);
    attn_kernel<<<grid, 256, ATTN_SMEM>>>(out);
}

// round 4
// speedup vs baseline: 3.4439x; 3.4439x over previous
#include <cuda_runtime.h>
#include <cuda_bf16.h>
#include <stdint.h>
#include <math.h>

#define HEAD 128
#define CEMB 64
#define BATCH 8
#define TLEN 4096
#define BT (BATCH * TLEN)

#define BM 128
#define BN 64
#define PITCHB 272          // smem row pitch in bytes (136 halves) — conflict-free ldmatrix

// ---------------- global scratch (static: allocation-guard safe) -------------
__device__ __nv_bfloat16 g_qh[(size_t)BT * HEAD];
__device__ __nv_bfloat16 g_ql[(size_t)BT * HEAD];
__device__ __nv_bfloat16 g_kh[(size_t)BT * HEAD];
__device__ __nv_bfloat16 g_kl[(size_t)BT * HEAD];
__device__ __nv_bfloat16 g_vh[(size_t)BT * HEAD];
__device__ __nv_bfloat16 g_vl[(size_t)BT * HEAD];

extern __shared__ char smem_raw[];

// ---------------- helpers ----------------------------------------------------
__device__ __forceinline__ uint32_t su32(const void* p) {
    uint32_t a;
    asm("{ .reg .u64 t; cvta.to.shared.u64 t, %1; cvt.u32.u64 %0, t; }"
        : "=r"(a) : "l"(p));
    return a;
}

__device__ __forceinline__ void mma_bf16(float* c, const uint32_t* a, const uint32_t* b) {
    asm volatile(
        "mma.sync.aligned.m16n8k16.row.col.f32.bf16.bf16.f32 "
        "{%0,%1,%2,%3}, {%4,%5,%6,%7}, {%8,%9}, {%0,%1,%2,%3};"
        : "+f"(c[0]), "+f"(c[1]), "+f"(c[2]), "+f"(c[3])
        : "r"(a[0]), "r"(a[1]), "r"(a[2]), "r"(a[3]), "r"(b[0]), "r"(b[1]));
}

__device__ __forceinline__ void ldsm4(uint32_t* r, uint32_t addr) {
    asm volatile("ldmatrix.sync.aligned.m8n8.x4.shared.b16 {%0,%1,%2,%3}, [%4];"
                 : "=r"(r[0]), "=r"(r[1]), "=r"(r[2]), "=r"(r[3]) : "r"(addr));
}
__device__ __forceinline__ void ldsm4t(uint32_t* r, uint32_t addr) {
    asm volatile("ldmatrix.sync.aligned.m8n8.x4.trans.shared.b16 {%0,%1,%2,%3}, [%4];"
                 : "=r"(r[0]), "=r"(r[1]), "=r"(r[2]), "=r"(r[3]) : "r"(addr));
}

__device__ __forceinline__ uint32_t pack2(__nv_bfloat16 a, __nv_bfloat16 b) {
    __nv_bfloat162 t = __halves2bfloat162(a, b);
    return *reinterpret_cast<uint32_t*>(&t);
}

// ---------------------------------------------------------------------------
// Kernel 1: fused QKV projection + bf16 hi/lo split (all row-major outputs).
// ---------------------------------------------------------------------------
#define PROJ_SMEM ((64 * 64 + 3 * 64 * 128) * sizeof(float))

__global__ __launch_bounds__(128) void proj_kernel(
    const float* __restrict__ x,
    const float* __restrict__ Wq,
    const float* __restrict__ Wk,
    const float* __restrict__ Wv)
{
    float* sm = (float*)smem_raw;
    float* xs = sm;
    float* wq = xs + 64 * 64;
    float* wk = wq + 64 * 128;
    float* wv = wk + 64 * 128;

    const int tid  = threadIdx.x;
    const int row0 = blockIdx.x * 64;

    for (int i = tid; i < 64 * 64 / 4; i += 128)
        ((float4*)xs)[i] = ((const float4*)(x + (size_t)row0 * CEMB))[i];
    for (int i = tid; i < 64 * 128 / 4; i += 128) {
        ((float4*)wq)[i] = ((const float4*)Wq)[i];
        ((float4*)wk)[i] = ((const float4*)Wk)[i];
        ((float4*)wv)[i] = ((const float4*)Wv)[i];
    }
    __syncthreads();

    const int h = tid;
    const float qscale = rsqrtf((float)HEAD);

    for (int r = 0; r < 64; r++) {
        float aq = 0.f, ak = 0.f, av = 0.f;
        #pragma unroll 16
        for (int c = 0; c < CEMB; c++) {
            float xv = xs[r * 64 + c];
            aq += xv * wq[c * 128 + h];
            ak += xv * wk[c * 128 + h];
            av += xv * wv[c * 128 + h];
        }
        size_t o = (size_t)(row0 + r) * HEAD + h;
        float qs = aq * qscale;
        __nv_bfloat16 qh = __float2bfloat16(qs);
        __nv_bfloat16 kh = __float2bfloat16(ak);
        __nv_bfloat16 vh = __float2bfloat16(av);
        g_qh[o] = qh; g_ql[o] = __float2bfloat16(qs - __bfloat162float(qh));
        g_kh[o] = kh; g_kl[o] = __float2bfloat16(ak - __bfloat162float(kh));
        g_vh[o] = vh; g_vl[o] = __float2bfloat16(av - __bfloat162float(vh));
    }
}

// ---------------------------------------------------------------------------
// Kernel 2: mma.sync bf16 split flash attention.
// grid (32, 8), 256 threads = 8 warps; warp w owns q-rows [q0+16w, q0+16w+16).
// ---------------------------------------------------------------------------
#define ATTN_SMEM (4 * 64 * PITCHB)

__global__ __launch_bounds__(256, 1) void attn_kernel(float* __restrict__ out)
{
    char* sm = smem_raw;
    const uint32_t sb = su32(sm);
    const int tid  = threadIdx.x;
    const int wid  = tid >> 5;
    const int lane = tid & 31;
    const int gid  = lane >> 2;      // 0..7
    const int tig  = lane & 3;       // 0..3
    const int qx   = 31 - (int)blockIdx.x;     // heavy tiles first
    const int b    = blockIdx.y;
    const int q0   = qx * BM;
    const int grow0 = q0 + wid * 16 + gid;      // rows: grow0 (c0,c1), grow0+8 (c2,c3)

    const uint32_t KH = sb;
    const uint32_t KL = KH + 64 * PITCHB;
    const uint32_t VH = KL + 64 * PITCHB;
    const uint32_t VL = VH + 64 * PITCHB;

    // ---- preload Q fragments (registers, reused every tile) ----
    uint32_t aqh[8][4], aql[8][4];
    {
        const size_t rb = (size_t)b * TLEN + grow0;
        #pragma unroll
        for (int kc = 0; kc < 8; kc++) {
            const int col = kc * 16 + 2 * tig;
            aqh[kc][0] = *(const uint32_t*)(g_qh + rb * HEAD + col);
            aqh[kc][1] = *(const uint32_t*)(g_qh + (rb + 8) * HEAD + col);
            aqh[kc][2] = *(const uint32_t*)(g_qh + rb * HEAD + col + 8);
            aqh[kc][3] = *(const uint32_t*)(g_qh + (rb + 8) * HEAD + col + 8);
            aql[kc][0] = *(const uint32_t*)(g_ql + rb * HEAD + col);
            aql[kc][1] = *(const uint32_t*)(g_ql + (rb + 8) * HEAD + col);
            aql[kc][2] = *(const uint32_t*)(g_ql + rb * HEAD + col + 8);
            aql[kc][3] = *(const uint32_t*)(g_ql + (rb + 8) * HEAD + col + 8);
        }
    }

    float o[16][4];
    #pragma unroll
    for (int i = 0; i < 16; i++)
        #pragma unroll
        for (int j = 0; j < 4; j++) o[i][j] = 0.f;
    float m0 = -3.0e38f, m1 = -3.0e38f, l0 = 0.f, l1 = 0.f;

    const int ntile = 2 * qx + 2;
    const __nv_bfloat16* kh_g = g_kh + (size_t)b * TLEN * HEAD;
    const __nv_bfloat16* kl_g = g_kl + (size_t)b * TLEN * HEAD;
    const __nv_bfloat16* vh_g = g_vh + (size_t)b * TLEN * HEAD;
    const __nv_bfloat16* vl_g = g_vl + (size_t)b * TLEN * HEAD;

    for (int t = 0; t < ntile; t++) {
        const int k0 = t * BN;
        __syncthreads();
        // ---- stage K/V hi+lo tiles into smem ----
        {
            const __nv_bfloat16* srcs[4] = {
                kh_g + (size_t)k0 * HEAD, kl_g + (size_t)k0 * HEAD,
                vh_g + (size_t)k0 * HEAD, vl_g + (size_t)k0 * HEAD };
            #pragma unroll
            for (int ii = 0; ii < 16; ii++) {
                int i = tid + ii * 256;
                int buf = i >> 10, j = i & 1023, r = j >> 4, c = j & 15;
                uint4 v = *(const uint4*)(srcs[buf] + (size_t)r * HEAD + c * 8);
                *(uint4*)(sm + buf * 64 * PITCHB + r * PITCHB + c * 16) = v;
            }
        }
        __syncthreads();

        // ---- S = Q K^T (3-term split) ----
        float s[8][4];
        #pragma unroll
        for (int i = 0; i < 8; i++)
            #pragma unroll
            for (int j = 0; j < 4; j++) s[i][j] = 0.f;

        #pragma unroll
        for (int kc = 0; kc < 8; kc++) {
            #pragma unroll
            for (int pp = 0; pp < 2; pp++) {
                uint32_t kh[2][4], kl[2][4];
                #pragma unroll
                for (int u = 0; u < 2; u++) {
                    const int p = 2 * pp + u;
                    const int i = lane & 7, sel = lane >> 3;
                    const uint32_t off =
                        (uint32_t)((16 * p + i + ((sel >> 1) << 3)) * PITCHB +
                                   (kc * 16 + ((sel & 1) << 3)) * 2);
                    ldsm4(kh[u], KH + off);
                    ldsm4(kl[u], KL + off);
                }
                #pragma unroll
                for (int term = 0; term < 3; term++) {
                    const uint32_t* a = (term == 2) ? aql[kc] : aqh[kc];
                    const uint32_t (*bb)[4] = (term == 1) ? kl : kh;
                    mma_bf16(s[4 * pp + 0], a, &bb[0][0]);
                    mma_bf16(s[4 * pp + 1], a, &bb[0][2]);
                    mma_bf16(s[4 * pp + 2], a, &bb[1][0]);
                    mma_bf16(s[4 * pp + 3], a, &bb[1][2]);
                }
            }
        }

        // ---- causal mask (only near the diagonal) ----
        if (k0 + 63 > grow0) {
            #pragma unroll
            for (int nb = 0; nb < 8; nb++) {
                #pragma unroll
                for (int j = 0; j < 2; j++) {
                    const int c = k0 + 8 * nb + 2 * tig + j;
                    if (c > grow0)     s[nb][j]     = -3.0e38f;
                    if (c > grow0 + 8) s[nb][2 + j] = -3.0e38f;
                }
            }
        }

        // ---- online softmax (register-resident, per 2 rows) ----
        float mx0 = m0, mx1 = m1;
        #pragma unroll
        for (int nb = 0; nb < 8; nb++) {
            mx0 = fmaxf(mx0, fmaxf(s[nb][0], s[nb][1]));
            mx1 = fmaxf(mx1, fmaxf(s[nb][2], s[nb][3]));
        }
        mx0 = fmaxf(mx0, __shfl_xor_sync(0xffffffffu, mx0, 1));
        mx0 = fmaxf(mx0, __shfl_xor_sync(0xffffffffu, mx0, 2));
        mx1 = fmaxf(mx1, __shfl_xor_sync(0xffffffffu, mx1, 1));
        mx1 = fmaxf(mx1, __shfl_xor_sync(0xffffffffu, mx1, 2));
        const float sf0 = __expf(m0 - mx0);
        const float sf1 = __expf(m1 - mx1);
        float sum0 = 0.f, sum1 = 0.f;
        #pragma unroll
        for (int nb = 0; nb < 8; nb++) {
            s[nb][0] = __expf(s[nb][0] - mx0);
            s[nb][1] = __expf(s[nb][1] - mx0);
            s[nb][2] = __expf(s[nb][2] - mx1);
            s[nb][3] = __expf(s[nb][3] - mx1);
            sum0 += s[nb][0] + s[nb][1];
            sum1 += s[nb][2] + s[nb][3];
        }
        sum0 += __shfl_xor_sync(0xffffffffu, sum0, 1);
        sum0 += __shfl_xor_sync(0xffffffffu, sum0, 2);
        sum1 += __shfl_xor_sync(0xffffffffu, sum1, 1);
        sum1 += __shfl_xor_sync(0xffffffffu, sum1, 2);
        l0 = l0 * sf0 + sum0;  l1 = l1 * sf1 + sum1;
        m0 = mx0;  m1 = mx1;

        #pragma unroll
        for (int nb = 0; nb < 16; nb++) {
            o[nb][0] *= sf0; o[nb][1] *= sf0;
            o[nb][2] *= sf1; o[nb][3] *= sf1;
        }

        // ---- P -> bf16 hi/lo fragments (C layout == next A layout) ----
        uint32_t pha[8], phb[8], pla[8], plb[8];
        #pragma unroll
        for (int nb = 0; nb < 8; nb++) {
            __nv_bfloat16 h0 = __float2bfloat16(s[nb][0]);
            __nv_bfloat16 h1 = __float2bfloat16(s[nb][1]);
            __nv_bfloat16 h2 = __float2bfloat16(s[nb][2]);
            __nv_bfloat16 h3 = __float2bfloat16(s[nb][3]);
            pha[nb] = pack2(h0, h1);
            phb[nb] = pack2(h2, h3);
            pla[nb] = pack2(__float2bfloat16(s[nb][0] - __bfloat162float(h0)),
                            __float2bfloat16(s[nb][1] - __bfloat162float(h1)));
            plb[nb] = pack2(__float2bfloat16(s[nb][2] - __bfloat162float(h2)),
                            __float2bfloat16(s[nb][3] - __bfloat162float(h3)));
        }

        // ---- O += P V (3-term split) ----
        #pragma unroll
        for (int kc = 0; kc < 4; kc++) {
            const uint32_t ah[4] = { pha[2 * kc], phb[2 * kc], pha[2 * kc + 1], phb[2 * kc + 1] };
            const uint32_t al[4] = { pla[2 * kc], plb[2 * kc], pla[2 * kc + 1], plb[2 * kc + 1] };
            #pragma unroll
            for (int qq = 0; qq < 4; qq++) {
                uint32_t vh[2][4], vl[2][4];
                #pragma unroll
                for (int u = 0; u < 2; u++) {
                    const int q = 2 * qq + u;
                    const int i = lane & 7, sel = lane >> 3;
                    const uint32_t off =
                        (uint32_t)((kc * 16 + i + ((sel & 1) << 3)) * PITCHB +
                                   (16 * q + ((sel >> 1) << 3)) * 2);
                    ldsm4t(vh[u], VH + off);
                    ldsm4t(vl[u], VL + off);
                }
                #pragma unroll
                for (int term = 0; term < 3; term++) {
                    const uint32_t* a = (term == 2) ? al : ah;
                    const uint32_t (*bb)[4] = (term == 1) ? vl : vh;
                    mma_bf16(o[4 * qq + 0], a, &bb[0][0]);
                    mma_bf16(o[4 * qq + 1], a, &bb[0][2]);
                    mma_bf16(o[4 * qq + 2], a, &bb[1][0]);
                    mma_bf16(o[4 * qq + 3], a, &bb[1][2]);
                }
            }
        }
    }

    // ---- epilogue ----
    const float inv0 = 1.f / l0;
    const float inv1 = 1.f / l1;
    float* og = out + ((size_t)b * TLEN + grow0) * HEAD;
    #pragma unroll
    for (int nb = 0; nb < 16; nb++) {
        const int col = 8 * nb + 2 * tig;
        float2 v0 = make_float2(o[nb][0] * inv0, o[nb][1] * inv0);
        float2 v1 = make_float2(o[nb][2] * inv1, o[nb][3] * inv1);
        *(float2*)(og + col) = v0;
        *(float2*)(og + 8 * HEAD + col) = v1;
    }
}

// ---------------------------------------------------------------------------
extern "C" void kernel_launch(void* const* d_in, const int* in_sizes, int n_in,
                              void* d_out, int out_size)
{
    (void)in_sizes; (void)n_in; (void)out_size;
    const float* x  = (const float*)d_in[0];
    const float* Wq = (const float*)d_in[1];
    const float* Wk = (const float*)d_in[2];
    const float* Wv = (const float*)d_in[3];
    float* out = (float*)d_out;

    cudaFuncSetAttribute(proj_kernel, cudaFuncAttributeMaxDynamicSharedMemorySize,
                         (int)PROJ_SMEM);
    cudaFuncSetAttribute(attn_kernel, cudaFuncAttributeMaxDynamicSharedMemorySize,
                         (int)ATTN_SMEM);

    proj_kernel<<<BT / 64, 128, PROJ_SMEM>>>(x, Wq, Wk, Wv);

    dim3 grid(TLEN / BM, BATCH);
    attn_kernel<<<grid, 256, ATTN_SMEM>>>(out);
}

// round 5
// speedup vs baseline: 4.2050x; 1.2210x over previous
#include <cuda_runtime.h>
#include <cuda_bf16.h>
#include <stdint.h>
#include <math.h>

#define HEAD 128
#define CEMB 64
#define BATCH 8
#define TLEN 4096
#define BT (BATCH * TLEN)

#define BM 128
#define BN 64
#define PITCHB 272          // attn smem row pitch bytes (68 banks -> 4-bank row step)

// ---------------- global scratch (static) ------------------------------------
__device__ __nv_bfloat16 g_qh[(size_t)BT * HEAD];
__device__ __nv_bfloat16 g_ql[(size_t)BT * HEAD];
__device__ __nv_bfloat16 g_kh[(size_t)BT * HEAD];
__device__ __nv_bfloat16 g_kl[(size_t)BT * HEAD];
__device__ __nv_bfloat16 g_vh[(size_t)BT * HEAD];
__device__ __nv_bfloat16 g_vl[(size_t)BT * HEAD];

extern __shared__ char smem_raw[];

// ---------------- helpers ----------------------------------------------------
__device__ __forceinline__ uint32_t su32(const void* p) {
    uint32_t a;
    asm("{ .reg .u64 t; cvta.to.shared.u64 t, %1; cvt.u32.u64 %0, t; }"
        : "=r"(a) : "l"(p));
    return a;
}

__device__ __forceinline__ void mma_bf16(float* c, const uint32_t* a, const uint32_t* b) {
    asm volatile(
        "mma.sync.aligned.m16n8k16.row.col.f32.bf16.bf16.f32 "
        "{%0,%1,%2,%3}, {%4,%5,%6,%7}, {%8,%9}, {%0,%1,%2,%3};"
        : "+f"(c[0]), "+f"(c[1]), "+f"(c[2]), "+f"(c[3])
        : "r"(a[0]), "r"(a[1]), "r"(a[2]), "r"(a[3]), "r"(b[0]), "r"(b[1]));
}

__device__ __forceinline__ void ldsm4(uint32_t* r, uint32_t addr) {
    asm volatile("ldmatrix.sync.aligned.m8n8.x4.shared.b16 {%0,%1,%2,%3}, [%4];"
                 : "=r"(r[0]), "=r"(r[1]), "=r"(r[2]), "=r"(r[3]) : "r"(addr));
}
__device__ __forceinline__ void ldsm4t(uint32_t* r, uint32_t addr) {
    asm volatile("ldmatrix.sync.aligned.m8n8.x4.trans.shared.b16 {%0,%1,%2,%3}, [%4];"
                 : "=r"(r[0]), "=r"(r[1]), "=r"(r[2]), "=r"(r[3]) : "r"(addr));
}

__device__ __forceinline__ uint32_t pack2(__nv_bfloat16 a, __nv_bfloat16 b) {
    __nv_bfloat162 t = __halves2bfloat162(a, b);
    return *reinterpret_cast<uint32_t*>(&t);
}

__device__ __forceinline__ float fexp2(float x) {
    float y;
    asm("ex2.approx.ftz.f32 %0, %1;" : "=f"(y) : "f"(x));
    return y;
}

#define CP_ASYNC16(dst, src) \
    asm volatile("cp.async.cg.shared.global [%0], [%1], 16;" :: "r"(dst), "l"(src))
#define CP_COMMIT() asm volatile("cp.async.commit_group;" ::: "memory")
#define CP_WAIT(n)  asm volatile("cp.async.wait_group %0;" :: "n"(n) : "memory")

__device__ __forceinline__ void split2(float v0, float v1, uint32_t& hi, uint32_t& lo) {
    __nv_bfloat16 h0 = __float2bfloat16(v0);
    __nv_bfloat16 h1 = __float2bfloat16(v1);
    hi = pack2(h0, h1);
    lo = pack2(__float2bfloat16(v0 - __bfloat162float(h0)),
               __float2bfloat16(v1 - __bfloat162float(h1)));
}

// ---------------------------------------------------------------------------
// Kernel 1: QKV projection on tensor cores (3-term split-bf16).
// grid = BT/128, 256 threads (8 warps); warp w owns rows [128*blk + 16w, +16).
// log2(e) folded into Wq scale so attn can use raw ex2.
// ---------------------------------------------------------------------------
#define XPITCH 144                     // bytes/row (72 halves)
#define WPITCH 784                     // bytes/row (392 halves)
#define P_XH 0
#define P_XL (128 * XPITCH)
#define P_WH (2 * 128 * XPITCH)
#define P_WL (P_WH + 64 * WPITCH)
#define PROJ_SMEM (P_WL + 64 * WPITCH)

__global__ __launch_bounds__(256) void proj_kernel(
    const float* __restrict__ x,
    const float* __restrict__ Wq,
    const float* __restrict__ Wk,
    const float* __restrict__ Wv)
{
    char* sm = smem_raw;
    const uint32_t sb = su32(sm);
    const int tid  = threadIdx.x;
    const int wid  = tid >> 5;
    const int lane = tid & 31;
    const int gid  = lane >> 2;
    const int tig  = lane & 3;
    const int row0 = blockIdx.x * 128;
    const float qsc = rsqrtf((float)HEAD) * 1.4426950408889634f;

    // ---- stage x -> xh/xl smem ----
    #pragma unroll
    for (int ii = 0; ii < 8; ii++) {
        int i = tid + ii * 256;             // 2048 float4
        int r = i >> 4, c4 = i & 15;
        float4 v = ((const float4*)(x + (size_t)(row0 + r) * CEMB))[c4];
        uint32_t h0, l0, h1, l1;
        split2(v.x, v.y, h0, l0);
        split2(v.z, v.w, h1, l1);
        char* d = sm + P_XH + r * XPITCH + c4 * 8;
        *(uint32_t*)d = h0; *(uint32_t*)(d + 4) = h1;
        char* d2 = sm + P_XL + r * XPITCH + c4 * 8;
        *(uint32_t*)d2 = l0; *(uint32_t*)(d2 + 4) = l1;
    }
    // ---- stage W (q|k|v concat, q pre-scaled) -> wh/wl smem ----
    #pragma unroll
    for (int ii = 0; ii < 24; ii++) {
        int i = tid + ii * 256;             // 6144 float4
        int r = i / 96, c4 = i % 96;
        int col = 4 * c4, a = col >> 7, lcol = col & 127;
        const float* ws = (a == 0 ? Wq : (a == 1 ? Wk : Wv)) + r * 128 + lcol;
        float4 v = *(const float4*)ws;
        if (a == 0) { v.x *= qsc; v.y *= qsc; v.z *= qsc; v.w *= qsc; }
        uint32_t h0, l0, h1, l1;
        split2(v.x, v.y, h0, l0);
        split2(v.z, v.w, h1, l1);
        char* d = sm + P_WH + r * WPITCH + col * 2;
        *(uint32_t*)d = h0; *(uint32_t*)(d + 4) = h1;
        char* d2 = sm + P_WL + r * WPITCH + col * 2;
        *(uint32_t*)d2 = l0; *(uint32_t*)(d2 + 4) = l1;
    }
    __syncthreads();

    // ---- A fragments (x rows, reused across all 6 col-chunks) ----
    const int wr0 = wid * 16;
    uint32_t axh[4][4], axl[4][4];
    {
        const int arow = (lane & 7) + ((lane >> 3) & 1) * 8;
        const int acol = (lane >> 4) * 8;
        #pragma unroll
        for (int ks = 0; ks < 4; ks++) {
            uint32_t ad = sb + P_XH + (wr0 + arow) * XPITCH + (ks * 16 + acol) * 2;
            ldsm4(axh[ks], ad);
            ldsm4(axl[ks], ad + (P_XL - P_XH));
        }
    }

    #pragma unroll
    for (int chunk = 0; chunk < 6; chunk++) {
        float c[8][4];
        #pragma unroll
        for (int i = 0; i < 8; i++)
            #pragma unroll
            for (int j = 0; j < 4; j++) c[i][j] = 0.f;

        #pragma unroll
        for (int ks = 0; ks < 4; ks++) {
            #pragma unroll
            for (int q = 0; q < 4; q++) {
                uint32_t wh[4], wl[4];
                const int i7 = lane & 7, sel = lane >> 3;
                uint32_t off = (uint32_t)((ks * 16 + i7 + ((sel & 1) << 3)) * WPITCH +
                                          (chunk * 64 + q * 16 + ((sel >> 1) << 3)) * 2);
                ldsm4t(wh, sb + P_WH + off);
                ldsm4t(wl, sb + P_WL + off);
                #pragma unroll
                for (int term = 0; term < 3; term++) {
                    const uint32_t* a = (term == 2) ? axl[ks] : axh[ks];
                    const uint32_t* bb = (term == 1) ? wl : wh;
                    mma_bf16(c[2 * q],     a, &bb[0]);
                    mma_bf16(c[2 * q + 1], a, &bb[2]);
                }
            }
        }

        // ---- write split outputs ----
        __nv_bfloat16 *dh, *dl;
        int colbase;
        if (chunk < 2)      { dh = g_qh; dl = g_ql; colbase = chunk * 64; }
        else if (chunk < 4) { dh = g_kh; dl = g_kl; colbase = (chunk - 2) * 64; }
        else                { dh = g_vh; dl = g_vl; colbase = (chunk - 4) * 64; }
        const size_t rb = (size_t)(row0 + wr0 + gid) * HEAD;
        #pragma unroll
        for (int nb = 0; nb < 8; nb++) {
            const int col = colbase + 8 * nb + 2 * tig;
            uint32_t h, l;
            split2(c[nb][0], c[nb][1], h, l);
            *(uint32_t*)(dh + rb + col) = h;
            *(uint32_t*)(dl + rb + col) = l;
            split2(c[nb][2], c[nb][3], h, l);
            *(uint32_t*)(dh + rb + 8 * HEAD + col) = h;
            *(uint32_t*)(dl + rb + 8 * HEAD + col) = l;
        }
    }
}

// ---------------------------------------------------------------------------
// Kernel 2: mma.sync split-bf16 flash attention, cp.async double-buffered.
// grid (32, 8), 256 threads = 8 warps.
// ---------------------------------------------------------------------------
#define BUFB (4 * 64 * PITCHB)         // one K/V hi+lo buffer set: 69632 B
#define ATTN_SMEM (2 * BUFB)

__global__ __launch_bounds__(256, 1) void attn_kernel(float* __restrict__ out)
{
    char* sm = smem_raw;
    const uint32_t sb = su32(sm);
    const int tid  = threadIdx.x;
    const int wid  = tid >> 5;
    const int lane = tid & 31;
    const int gid  = lane >> 2;
    const int tig  = lane & 3;
    const int qx   = 31 - (int)blockIdx.x;
    const int b    = blockIdx.y;
    const int q0   = qx * BM;
    const int grow0 = q0 + wid * 16 + gid;
    const int wrow_max = q0 + wid * 16 + 15;

    // ---- preload Q fragments ----
    uint32_t aqh[8][4], aql[8][4];
    {
        const size_t rb = (size_t)b * TLEN + grow0;
        #pragma unroll
        for (int kc = 0; kc < 8; kc++) {
            const int col = kc * 16 + 2 * tig;
            aqh[kc][0] = *(const uint32_t*)(g_qh + rb * HEAD + col);
            aqh[kc][1] = *(const uint32_t*)(g_qh + (rb + 8) * HEAD + col);
            aqh[kc][2] = *(const uint32_t*)(g_qh + rb * HEAD + col + 8);
            aqh[kc][3] = *(const uint32_t*)(g_qh + (rb + 8) * HEAD + col + 8);
            aql[kc][0] = *(const uint32_t*)(g_ql + rb * HEAD + col);
            aql[kc][1] = *(const uint32_t*)(g_ql + (rb + 8) * HEAD + col);
            aql[kc][2] = *(const uint32_t*)(g_ql + rb * HEAD + col + 8);
            aql[kc][3] = *(const uint32_t*)(g_ql + (rb + 8) * HEAD + col + 8);
        }
    }

    float o[16][4];
    #pragma unroll
    for (int i = 0; i < 16; i++)
        #pragma unroll
        for (int j = 0; j < 4; j++) o[i][j] = 0.f;
    float m0 = -3.0e38f, m1 = -3.0e38f, l0 = 0.f, l1 = 0.f;

    const int ntile = 2 * qx + 2;
    const __nv_bfloat16* kh_g = g_kh + (size_t)b * TLEN * HEAD;
    const __nv_bfloat16* kl_g = g_kl + (size_t)b * TLEN * HEAD;
    const __nv_bfloat16* vh_g = g_vh + (size_t)b * TLEN * HEAD;
    const __nv_bfloat16* vl_g = g_vl + (size_t)b * TLEN * HEAD;

    // staging lambda (16B cp.async x16 per thread = one 4-buffer tile set)
    auto stage = [&](int buf, int t) {
        const int k0 = t * BN;
        const __nv_bfloat16* srcs[4] = {
            kh_g + (size_t)k0 * HEAD, kl_g + (size_t)k0 * HEAD,
            vh_g + (size_t)k0 * HEAD, vl_g + (size_t)k0 * HEAD };
        const uint32_t d0 = sb + buf * BUFB;
        #pragma unroll
        for (int ii = 0; ii < 16; ii++) {
            int i = tid + ii * 256;
            int sub = i >> 10, j = i & 1023, r = j >> 4, c = j & 15;
            const void* src = (const void*)(srcs[sub] + (size_t)r * HEAD + c * 8);
            uint32_t dst = d0 + sub * 64 * PITCHB + r * PITCHB + c * 16;
            CP_ASYNC16(dst, src);
        }
        CP_COMMIT();
    };

    stage(0, 0);

    for (int t = 0; t < ntile; t++) {
        const int k0 = t * BN;
        const int buf = t & 1;
        if (t + 1 < ntile) { stage(buf ^ 1, t + 1); CP_WAIT(1); }
        else               { CP_WAIT(0); }
        __syncthreads();

        const uint32_t KH = sb + buf * BUFB;
        const uint32_t KL = KH + 64 * PITCHB;
        const uint32_t VH = KL + 64 * PITCHB;
        const uint32_t VL = VH + 64 * PITCHB;

        if (k0 <= wrow_max) {   // warp-uniform: skip fully-masked warp-tiles
            // ---- S = Q K^T (3-term split) ----
            float s[8][4];
            #pragma unroll
            for (int i = 0; i < 8; i++)
                #pragma unroll
                for (int j = 0; j < 4; j++) s[i][j] = 0.f;

            #pragma unroll
            for (int kc = 0; kc < 8; kc++) {
                #pragma unroll
                for (int pp = 0; pp < 2; pp++) {
                    uint32_t kh[2][4], kl[2][4];
                    #pragma unroll
                    for (int u = 0; u < 2; u++) {
                        const int p = 2 * pp + u;
                        const int i = lane & 7, sel = lane >> 3;
                        const uint32_t off =
                            (uint32_t)((16 * p + i + ((sel >> 1) << 3)) * PITCHB +
                                       (kc * 16 + ((sel & 1) << 3)) * 2);
                        ldsm4(kh[u], KH + off);
                        ldsm4(kl[u], KL + off);
                    }
                    #pragma unroll
                    for (int term = 0; term < 3; term++) {
                        const uint32_t* a = (term == 2) ? aql[kc] : aqh[kc];
                        const uint32_t (*bb)[4] = (term == 1) ? kl : kh;
                        mma_bf16(s[4 * pp + 0], a, &bb[0][0]);
                        mma_bf16(s[4 * pp + 1], a, &bb[0][2]);
                        mma_bf16(s[4 * pp + 2], a, &bb[1][0]);
                        mma_bf16(s[4 * pp + 3], a, &bb[1][2]);
                    }
                }
            }

            // ---- causal mask ----
            if (k0 + 63 > grow0) {
                #pragma unroll
                for (int nb = 0; nb < 8; nb++) {
                    #pragma unroll
                    for (int j = 0; j < 2; j++) {
                        const int c = k0 + 8 * nb + 2 * tig + j;
                        if (c > grow0)     s[nb][j]     = -3.0e38f;
                        if (c > grow0 + 8) s[nb][2 + j] = -3.0e38f;
                    }
                }
            }

            // ---- online softmax (base-2; log2e folded into Q) ----
            float mx0 = m0, mx1 = m1;
            #pragma unroll
            for (int nb = 0; nb < 8; nb++) {
                mx0 = fmaxf(mx0, fmaxf(s[nb][0], s[nb][1]));
                mx1 = fmaxf(mx1, fmaxf(s[nb][2], s[nb][3]));
            }
            mx0 = fmaxf(mx0, __shfl_xor_sync(0xffffffffu, mx0, 1));
            mx0 = fmaxf(mx0, __shfl_xor_sync(0xffffffffu, mx0, 2));
            mx1 = fmaxf(mx1, __shfl_xor_sync(0xffffffffu, mx1, 1));
            mx1 = fmaxf(mx1, __shfl_xor_sync(0xffffffffu, mx1, 2));
            const float sf0 = fexp2(m0 - mx0);
            const float sf1 = fexp2(m1 - mx1);
            float sum0 = 0.f, sum1 = 0.f;
            #pragma unroll
            for (int nb = 0; nb < 8; nb++) {
                s[nb][0] = fexp2(s[nb][0] - mx0);
                s[nb][1] = fexp2(s[nb][1] - mx0);
                s[nb][2] = fexp2(s[nb][2] - mx1);
                s[nb][3] = fexp2(s[nb][3] - mx1);
                sum0 += s[nb][0] + s[nb][1];
                sum1 += s[nb][2] + s[nb][3];
            }
            sum0 += __shfl_xor_sync(0xffffffffu, sum0, 1);
            sum0 += __shfl_xor_sync(0xffffffffu, sum0, 2);
            sum1 += __shfl_xor_sync(0xffffffffu, sum1, 1);
            sum1 += __shfl_xor_sync(0xffffffffu, sum1, 2);
            l0 = l0 * sf0 + sum0;  l1 = l1 * sf1 + sum1;
            m0 = mx0;  m1 = mx1;

            #pragma unroll
            for (int nb = 0; nb < 16; nb++) {
                o[nb][0] *= sf0; o[nb][1] *= sf0;
                o[nb][2] *= sf1; o[nb][3] *= sf1;
            }

            // ---- P -> bf16 hi/lo fragments ----
            uint32_t pha[8], phb[8], pla[8], plb[8];
            #pragma unroll
            for (int nb = 0; nb < 8; nb++) {
                split2(s[nb][0], s[nb][1], pha[nb], pla[nb]);
                split2(s[nb][2], s[nb][3], phb[nb], plb[nb]);
            }

            // ---- O += P V (3-term split) ----
            #pragma unroll
            for (int kc = 0; kc < 4; kc++) {
                const uint32_t ah[4] = { pha[2 * kc], phb[2 * kc], pha[2 * kc + 1], phb[2 * kc + 1] };
                const uint32_t al[4] = { pla[2 * kc], plb[2 * kc], pla[2 * kc + 1], plb[2 * kc + 1] };
                #pragma unroll
                for (int qq = 0; qq < 4; qq++) {
                    uint32_t vh[2][4], vl[2][4];
                    #pragma unroll
                    for (int u = 0; u < 2; u++) {
                        const int q = 2 * qq + u;
                        const int i = lane & 7, sel = lane >> 3;
                        const uint32_t off =
                            (uint32_t)((kc * 16 + i + ((sel & 1) << 3)) * PITCHB +
                                       (16 * q + ((sel >> 1) << 3)) * 2);
                        ldsm4t(vh[u], VH + off);
                        ldsm4t(vl[u], VL + off);
                    }
                    #pragma unroll
                    for (int term = 0; term < 3; term++) {
                        const uint32_t* a = (term == 2) ? al : ah;
                        const uint32_t (*bb)[4] = (term == 1) ? vl : vh;
                        mma_bf16(o[4 * qq + 0], a, &bb[0][0]);
                        mma_bf16(o[4 * qq + 1], a, &bb[0][2]);
                        mma_bf16(o[4 * qq + 2], a, &bb[1][0]);
                        mma_bf16(o[4 * qq + 3], a, &bb[1][2]);
                    }
                }
            }
        }
        __syncthreads();
    }

    // ---- epilogue ----
    const float inv0 = 1.f / l0;
    const float inv1 = 1.f / l1;
    float* og = out + ((size_t)b * TLEN + grow0) * HEAD;
    #pragma unroll
    for (int nb = 0; nb < 16; nb++) {
        const int col = 8 * nb + 2 * tig;
        *(float2*)(og + col)            = make_float2(o[nb][0] * inv0, o[nb][1] * inv0);
        *(float2*)(og + 8 * HEAD + col) = make_float2(o[nb][2] * inv1, o[nb][3] * inv1);
    }
}

// ---------------------------------------------------------------------------
extern "C" void kernel_launch(void* const* d_in, const int* in_sizes, int n_in,
                              void* d_out, int out_size)
{
    (void)in_sizes; (void)n_in; (void)out_size;
    const float* x  = (const float*)d_in[0];
    const float* Wq = (const float*)d_in[1];
    const float* Wk = (const float*)d_in[2];
    const float* Wv = (const float*)d_in[3];
    float* out = (float*)d_out;

    cudaFuncSetAttribute(proj_kernel, cudaFuncAttributeMaxDynamicSharedMemorySize,
                         (int)PROJ_SMEM);
    cudaFuncSetAttribute(attn_kernel, cudaFuncAttributeMaxDynamicSharedMemorySize,
                         (int)ATTN_SMEM);

    proj_kernel<<<BT / 128, 256, PROJ_SMEM>>>(x, Wq, Wk, Wv);

    dim3 grid(TLEN / BM, BATCH);
    attn_kernel<<<grid, 256, ATTN_SMEM>>>(out);
}

// round 6
// speedup vs baseline: 4.9246x; 1.1711x over previous
#include <cuda_runtime.h>
#include <cuda_bf16.h>
#include <stdint.h>
#include <math.h>

#define HEAD 128
#define CEMB 64
#define BATCH 8
#define TLEN 4096
#define BT (BATCH * TLEN)

#define BM 128
#define BN 64
#define PITCHB 272

// ---------------- global scratch (static) ------------------------------------
__device__ __nv_bfloat16 g_qh[(size_t)BT * HEAD];
__device__ __nv_bfloat16 g_ql[(size_t)BT * HEAD];
__device__ __nv_bfloat16 g_kh[(size_t)BT * HEAD];
__device__ __nv_bfloat16 g_kl[(size_t)BT * HEAD];
__device__ __nv_bfloat16 g_vh[(size_t)BT * HEAD];
__device__ __nv_bfloat16 g_vl[(size_t)BT * HEAD];

extern __shared__ char smem_raw[];

// ---------------- helpers ----------------------------------------------------
__device__ __forceinline__ uint32_t su32(const void* p) {
    uint32_t a;
    asm("{ .reg .u64 t; cvta.to.shared.u64 t, %1; cvt.u32.u64 %0, t; }"
        : "=r"(a) : "l"(p));
    return a;
}

__device__ __forceinline__ void mma_bf16(float* c, const uint32_t* a, const uint32_t* b) {
    asm volatile(
        "mma.sync.aligned.m16n8k16.row.col.f32.bf16.bf16.f32 "
        "{%0,%1,%2,%3}, {%4,%5,%6,%7}, {%8,%9}, {%0,%1,%2,%3};"
        : "+f"(c[0]), "+f"(c[1]), "+f"(c[2]), "+f"(c[3])
        : "r"(a[0]), "r"(a[1]), "r"(a[2]), "r"(a[3]), "r"(b[0]), "r"(b[1]));
}

__device__ __forceinline__ void ldsm4(uint32_t* r, uint32_t addr) {
    asm volatile("ldmatrix.sync.aligned.m8n8.x4.shared.b16 {%0,%1,%2,%3}, [%4];"
                 : "=r"(r[0]), "=r"(r[1]), "=r"(r[2]), "=r"(r[3]) : "r"(addr));
}
__device__ __forceinline__ void ldsm4t(uint32_t* r, uint32_t addr) {
    asm volatile("ldmatrix.sync.aligned.m8n8.x4.trans.shared.b16 {%0,%1,%2,%3}, [%4];"
                 : "=r"(r[0]), "=r"(r[1]), "=r"(r[2]), "=r"(r[3]) : "r"(addr));
}

__device__ __forceinline__ uint32_t pack2(__nv_bfloat16 a, __nv_bfloat16 b) {
    __nv_bfloat162 t = __halves2bfloat162(a, b);
    return *reinterpret_cast<uint32_t*>(&t);
}

__device__ __forceinline__ float fexp2(float x) {
    float y;
    asm("ex2.approx.ftz.f32 %0, %1;" : "=f"(y) : "f"(x));
    return y;
}

#define CP_ASYNC16(dst, src) \
    asm volatile("cp.async.cg.shared.global [%0], [%1], 16;" :: "r"(dst), "l"(src))
#define CP_COMMIT() asm volatile("cp.async.commit_group;" ::: "memory")
#define CP_WAIT(n)  asm volatile("cp.async.wait_group %0;" :: "n"(n) : "memory")

__device__ __forceinline__ void split2(float v0, float v1, uint32_t& hi, uint32_t& lo) {
    __nv_bfloat16 h0 = __float2bfloat16(v0);
    __nv_bfloat16 h1 = __float2bfloat16(v1);
    hi = pack2(h0, h1);
    lo = pack2(__float2bfloat16(v0 - __bfloat162float(h0)),
               __float2bfloat16(v1 - __bfloat162float(h1)));
}

// ---------------------------------------------------------------------------
// Kernel 1: QKV projection on tensor cores (3-term split-bf16).
// log2(e) folded into Wq so attn softmax uses raw ex2.
// ---------------------------------------------------------------------------
#define XPITCH 144
#define WPITCH 784
#define P_XH 0
#define P_XL (128 * XPITCH)
#define P_WH (2 * 128 * XPITCH)
#define P_WL (P_WH + 64 * WPITCH)
#define PROJ_SMEM (P_WL + 64 * WPITCH)

__global__ __launch_bounds__(256) void proj_kernel(
    const float* __restrict__ x,
    const float* __restrict__ Wq,
    const float* __restrict__ Wk,
    const float* __restrict__ Wv)
{
    char* sm = smem_raw;
    const uint32_t sb = su32(sm);
    const int tid  = threadIdx.x;
    const int wid  = tid >> 5;
    const int lane = tid & 31;
    const int gid  = lane >> 2;
    const int tig  = lane & 3;
    const int row0 = blockIdx.x * 128;
    const float qsc = rsqrtf((float)HEAD) * 1.4426950408889634f;

    #pragma unroll
    for (int ii = 0; ii < 8; ii++) {
        int i = tid + ii * 256;
        int r = i >> 4, c4 = i & 15;
        float4 v = ((const float4*)(x + (size_t)(row0 + r) * CEMB))[c4];
        uint32_t h0, l0, h1, l1;
        split2(v.x, v.y, h0, l0);
        split2(v.z, v.w, h1, l1);
        char* d = sm + P_XH + r * XPITCH + c4 * 8;
        *(uint32_t*)d = h0; *(uint32_t*)(d + 4) = h1;
        char* d2 = sm + P_XL + r * XPITCH + c4 * 8;
        *(uint32_t*)d2 = l0; *(uint32_t*)(d2 + 4) = l1;
    }
    #pragma unroll
    for (int ii = 0; ii < 24; ii++) {
        int i = tid + ii * 256;
        int r = i / 96, c4 = i % 96;
        int col = 4 * c4, a = col >> 7, lcol = col & 127;
        const float* ws = (a == 0 ? Wq : (a == 1 ? Wk : Wv)) + r * 128 + lcol;
        float4 v = *(const float4*)ws;
        if (a == 0) { v.x *= qsc; v.y *= qsc; v.z *= qsc; v.w *= qsc; }
        uint32_t h0, l0, h1, l1;
        split2(v.x, v.y, h0, l0);
        split2(v.z, v.w, h1, l1);
        char* d = sm + P_WH + r * WPITCH + col * 2;
        *(uint32_t*)d = h0; *(uint32_t*)(d + 4) = h1;
        char* d2 = sm + P_WL + r * WPITCH + col * 2;
        *(uint32_t*)d2 = l0; *(uint32_t*)(d2 + 4) = l1;
    }
    __syncthreads();

    const int wr0 = wid * 16;
    uint32_t axh[4][4], axl[4][4];
    {
        const int arow = (lane & 7) + ((lane >> 3) & 1) * 8;
        const int acol = (lane >> 4) * 8;
        #pragma unroll
        for (int ks = 0; ks < 4; ks++) {
            uint32_t ad = sb + P_XH + (wr0 + arow) * XPITCH + (ks * 16 + acol) * 2;
            ldsm4(axh[ks], ad);
            ldsm4(axl[ks], ad + (P_XL - P_XH));
        }
    }

    #pragma unroll
    for (int chunk = 0; chunk < 6; chunk++) {
        float c[8][4];
        #pragma unroll
        for (int i = 0; i < 8; i++)
            #pragma unroll
            for (int j = 0; j < 4; j++) c[i][j] = 0.f;

        #pragma unroll
        for (int ks = 0; ks < 4; ks++) {
            #pragma unroll
            for (int q = 0; q < 4; q++) {
                uint32_t wh[4], wl[4];
                const int i7 = lane & 7, sel = lane >> 3;
                uint32_t off = (uint32_t)((ks * 16 + i7 + ((sel & 1) << 3)) * WPITCH +
                                          (chunk * 64 + q * 16 + ((sel >> 1) << 3)) * 2);
                ldsm4t(wh, sb + P_WH + off);
                ldsm4t(wl, sb + P_WL + off);
                #pragma unroll
                for (int term = 0; term < 3; term++) {
                    const uint32_t* a = (term == 2) ? axl[ks] : axh[ks];
                    const uint32_t* bb = (term == 1) ? wl : wh;
                    mma_bf16(c[2 * q],     a, &bb[0]);
                    mma_bf16(c[2 * q + 1], a, &bb[2]);
                }
            }
        }

        __nv_bfloat16 *dh, *dl;
        int colbase;
        if (chunk < 2)      { dh = g_qh; dl = g_ql; colbase = chunk * 64; }
        else if (chunk < 4) { dh = g_kh; dl = g_kl; colbase = (chunk - 2) * 64; }
        else                { dh = g_vh; dl = g_vl; colbase = (chunk - 4) * 64; }
        const size_t rb = (size_t)(row0 + wr0 + gid) * HEAD;
        #pragma unroll
        for (int nb = 0; nb < 8; nb++) {
            const int col = colbase + 8 * nb + 2 * tig;
            uint32_t h, l;
            split2(c[nb][0], c[nb][1], h, l);
            *(uint32_t*)(dh + rb + col) = h;
            *(uint32_t*)(dl + rb + col) = l;
            split2(c[nb][2], c[nb][3], h, l);
            *(uint32_t*)(dh + rb + 8 * HEAD + col) = h;
            *(uint32_t*)(dl + rb + 8 * HEAD + col) = l;
        }
    }
}

// ---------------------------------------------------------------------------
// Kernel 2: mma.sync split-bf16 flash attention.
// 3-buffer cp.async ring, ONE __syncthreads per tile, PV = 2 terms (Ph only).
// ---------------------------------------------------------------------------
#define BUFB (4 * 64 * PITCHB)         // 69632 B per K/V hi+lo set
#define NBUF 3
#define ATTN_SMEM (NBUF * BUFB)        // 208896 B

__global__ __launch_bounds__(256, 1) void attn_kernel(float* __restrict__ out)
{
    char* sm = smem_raw;
    const uint32_t sb = su32(sm);
    const int tid  = threadIdx.x;
    const int wid  = tid >> 5;
    const int lane = tid & 31;
    const int gid  = lane >> 2;
    const int tig  = lane & 3;
    const int qx   = 31 - (int)blockIdx.x;
    const int b    = blockIdx.y;
    const int q0   = qx * BM;
    const int grow0 = q0 + wid * 16 + gid;
    const int wrow_max = q0 + wid * 16 + 15;

    // ---- preload Q fragments ----
    uint32_t aqh[8][4], aql[8][4];
    {
        const size_t rb = (size_t)b * TLEN + grow0;
        #pragma unroll
        for (int kc = 0; kc < 8; kc++) {
            const int col = kc * 16 + 2 * tig;
            aqh[kc][0] = *(const uint32_t*)(g_qh + rb * HEAD + col);
            aqh[kc][1] = *(const uint32_t*)(g_qh + (rb + 8) * HEAD + col);
            aqh[kc][2] = *(const uint32_t*)(g_qh + rb * HEAD + col + 8);
            aqh[kc][3] = *(const uint32_t*)(g_qh + (rb + 8) * HEAD + col + 8);
            aql[kc][0] = *(const uint32_t*)(g_ql + rb * HEAD + col);
            aql[kc][1] = *(const uint32_t*)(g_ql + (rb + 8) * HEAD + col);
            aql[kc][2] = *(const uint32_t*)(g_ql + rb * HEAD + col + 8);
            aql[kc][3] = *(const uint32_t*)(g_ql + (rb + 8) * HEAD + col + 8);
        }
    }

    float o[16][4];
    #pragma unroll
    for (int i = 0; i < 16; i++)
        #pragma unroll
        for (int j = 0; j < 4; j++) o[i][j] = 0.f;
    float m0 = -3.0e38f, m1 = -3.0e38f, l0 = 0.f, l1 = 0.f;

    const int ntile = 2 * qx + 2;
    const __nv_bfloat16* kh_g = g_kh + (size_t)b * TLEN * HEAD;
    const __nv_bfloat16* kl_g = g_kl + (size_t)b * TLEN * HEAD;
    const __nv_bfloat16* vh_g = g_vh + (size_t)b * TLEN * HEAD;
    const __nv_bfloat16* vl_g = g_vl + (size_t)b * TLEN * HEAD;

    auto stage = [&](int buf, int t) {
        const int k0 = t * BN;
        const __nv_bfloat16* srcs[4] = {
            kh_g + (size_t)k0 * HEAD, kl_g + (size_t)k0 * HEAD,
            vh_g + (size_t)k0 * HEAD, vl_g + (size_t)k0 * HEAD };
        const uint32_t d0 = sb + buf * BUFB;
        #pragma unroll
        for (int ii = 0; ii < 16; ii++) {
            int i = tid + ii * 256;
            int sub = i >> 10, j = i & 1023, r = j >> 4, c = j & 15;
            const void* src = (const void*)(srcs[sub] + (size_t)r * HEAD + c * 8);
            uint32_t dst = d0 + sub * 64 * PITCHB + r * PITCHB + c * 16;
            CP_ASYNC16(dst, src);
        }
        CP_COMMIT();
    };

    stage(0, 0);
    if (ntile > 1) stage(1, 1);

    int bufidx = 0;
    for (int t = 0; t < ntile; t++) {
        const int k0 = t * BN;
        // wait for tile t's data (one newer group may remain in flight)
        if (t + 1 < ntile) { CP_WAIT(1); } else { CP_WAIT(0); }
        __syncthreads();   // single barrier per tile: publishes buf(t), retires buf(t-1)
        if (t + 2 < ntile) {
            int nb = bufidx + 2; if (nb >= NBUF) nb -= NBUF;
            stage(nb, t + 2);
        }

        const uint32_t KH = sb + bufidx * BUFB;
        const uint32_t KL = KH + 64 * PITCHB;
        const uint32_t VH = KL + 64 * PITCHB;
        const uint32_t VL = VH + 64 * PITCHB;
        if (++bufidx == NBUF) bufidx = 0;

        if (k0 <= wrow_max) {
            // ---- S = Q K^T (3-term split) ----
            float s[8][4];
            #pragma unroll
            for (int i = 0; i < 8; i++)
                #pragma unroll
                for (int j = 0; j < 4; j++) s[i][j] = 0.f;

            #pragma unroll
            for (int kc = 0; kc < 8; kc++) {
                #pragma unroll
                for (int pp = 0; pp < 2; pp++) {
                    uint32_t kh[2][4], kl[2][4];
                    #pragma unroll
                    for (int u = 0; u < 2; u++) {
                        const int p = 2 * pp + u;
                        const int i = lane & 7, sel = lane >> 3;
                        const uint32_t off =
                            (uint32_t)((16 * p + i + ((sel >> 1) << 3)) * PITCHB +
                                       (kc * 16 + ((sel & 1) << 3)) * 2);
                        ldsm4(kh[u], KH + off);
                        ldsm4(kl[u], KL + off);
                    }
                    #pragma unroll
                    for (int term = 0; term < 3; term++) {
                        const uint32_t* a = (term == 2) ? aql[kc] : aqh[kc];
                        const uint32_t (*bb)[4] = (term == 1) ? kl : kh;
                        mma_bf16(s[4 * pp + 0], a, &bb[0][0]);
                        mma_bf16(s[4 * pp + 1], a, &bb[0][2]);
                        mma_bf16(s[4 * pp + 2], a, &bb[1][0]);
                        mma_bf16(s[4 * pp + 3], a, &bb[1][2]);
                    }
                }
            }

            // ---- causal mask ----
            if (k0 + 63 > grow0) {
                #pragma unroll
                for (int nb = 0; nb < 8; nb++) {
                    #pragma unroll
                    for (int j = 0; j < 2; j++) {
                        const int c = k0 + 8 * nb + 2 * tig + j;
                        if (c > grow0)     s[nb][j]     = -3.0e38f;
                        if (c > grow0 + 8) s[nb][2 + j] = -3.0e38f;
                    }
                }
            }

            // ---- online softmax (base-2) ----
            float mx0 = m0, mx1 = m1;
            #pragma unroll
            for (int nb = 0; nb < 8; nb++) {
                mx0 = fmaxf(mx0, fmaxf(s[nb][0], s[nb][1]));
                mx1 = fmaxf(mx1, fmaxf(s[nb][2], s[nb][3]));
            }
            mx0 = fmaxf(mx0, __shfl_xor_sync(0xffffffffu, mx0, 1));
            mx0 = fmaxf(mx0, __shfl_xor_sync(0xffffffffu, mx0, 2));
            mx1 = fmaxf(mx1, __shfl_xor_sync(0xffffffffu, mx1, 1));
            mx1 = fmaxf(mx1, __shfl_xor_sync(0xffffffffu, mx1, 2));
            const float sf0 = fexp2(m0 - mx0);
            const float sf1 = fexp2(m1 - mx1);
            float sum0 = 0.f, sum1 = 0.f;
            #pragma unroll
            for (int nb = 0; nb < 8; nb++) {
                s[nb][0] = fexp2(s[nb][0] - mx0);
                s[nb][1] = fexp2(s[nb][1] - mx0);
                s[nb][2] = fexp2(s[nb][2] - mx1);
                s[nb][3] = fexp2(s[nb][3] - mx1);
                sum0 += s[nb][0] + s[nb][1];
                sum1 += s[nb][2] + s[nb][3];
            }
            sum0 += __shfl_xor_sync(0xffffffffu, sum0, 1);
            sum0 += __shfl_xor_sync(0xffffffffu, sum0, 2);
            sum1 += __shfl_xor_sync(0xffffffffu, sum1, 1);
            sum1 += __shfl_xor_sync(0xffffffffu, sum1, 2);
            l0 = l0 * sf0 + sum0;  l1 = l1 * sf1 + sum1;
            m0 = mx0;  m1 = mx1;

            #pragma unroll
            for (int nb = 0; nb < 16; nb++) {
                o[nb][0] *= sf0; o[nb][1] *= sf0;
                o[nb][2] *= sf1; o[nb][3] *= sf1;
            }

            // ---- P -> bf16 hi fragments only (lo dropped: linear path) ----
            uint32_t pha[8], phb[8];
            #pragma unroll
            for (int nb = 0; nb < 8; nb++) {
                pha[nb] = pack2(__float2bfloat16(s[nb][0]), __float2bfloat16(s[nb][1]));
                phb[nb] = pack2(__float2bfloat16(s[nb][2]), __float2bfloat16(s[nb][3]));
            }

            // ---- O += Ph*(Vh + Vl)  (2 terms) ----
            #pragma unroll
            for (int kc = 0; kc < 4; kc++) {
                const uint32_t ah[4] = { pha[2 * kc], phb[2 * kc], pha[2 * kc + 1], phb[2 * kc + 1] };
                #pragma unroll
                for (int qq = 0; qq < 4; qq++) {
                    uint32_t vh[2][4], vl[2][4];
                    #pragma unroll
                    for (int u = 0; u < 2; u++) {
                        const int q = 2 * qq + u;
                        const int i = lane & 7, sel = lane >> 3;
                        const uint32_t off =
                            (uint32_t)((kc * 16 + i + ((sel & 1) << 3)) * PITCHB +
                                       (16 * q + ((sel >> 1) << 3)) * 2);
                        ldsm4t(vh[u], VH + off);
                        ldsm4t(vl[u], VL + off);
                    }
                    mma_bf16(o[4 * qq + 0], ah, &vh[0][0]);
                    mma_bf16(o[4 * qq + 1], ah, &vh[0][2]);
                    mma_bf16(o[4 * qq + 2], ah, &vh[1][0]);
                    mma_bf16(o[4 * qq + 3], ah, &vh[1][2]);
                    mma_bf16(o[4 * qq + 0], ah, &vl[0][0]);
                    mma_bf16(o[4 * qq + 1], ah, &vl[0][2]);
                    mma_bf16(o[4 * qq + 2], ah, &vl[1][0]);
                    mma_bf16(o[4 * qq + 3], ah, &vl[1][2]);
                }
            }
        }
    }

    // ---- epilogue ----
    const float inv0 = 1.f / l0;
    const float inv1 = 1.f / l1;
    float* og = out + ((size_t)b * TLEN + grow0) * HEAD;
    #pragma unroll
    for (int nb = 0; nb < 16; nb++) {
        const int col = 8 * nb + 2 * tig;
        *(float2*)(og + col)            = make_float2(o[nb][0] * inv0, o[nb][1] * inv0);
        *(float2*)(og + 8 * HEAD + col) = make_float2(o[nb][2] * inv1, o[nb][3] * inv1);
    }
}

// ---------------------------------------------------------------------------
extern "C" void kernel_launch(void* const* d_in, const int* in_sizes, int n_in,
                              void* d_out, int out_size)
{
    (void)in_sizes; (void)n_in; (void)out_size;
    const float* x  = (const float*)d_in[0];
    const float* Wq = (const float*)d_in[1];
    const float* Wk = (const float*)d_in[2];
    const float* Wv = (const float*)d_in[3];
    float* out = (float*)d_out;

    cudaFuncSetAttribute(proj_kernel, cudaFuncAttributeMaxDynamicSharedMemorySize,
                         (int)PROJ_SMEM);
    cudaFuncSetAttribute(attn_kernel, cudaFuncAttributeMaxDynamicSharedMemorySize,
                         (int)ATTN_SMEM);

    proj_kernel<<<BT / 128, 256, PROJ_SMEM>>>(x, Wq, Wk, Wv);

    dim3 grid(TLEN / BM, BATCH);
    attn_kernel<<<grid, 256, ATTN_SMEM>>>(out);
}

// round 7
// speedup vs baseline: 6.5404x; 1.3281x over previous
#include <cuda_runtime.h>
#include <cuda_bf16.h>
#include <cuda_fp16.h>
#include <stdint.h>
#include <math.h>

#define HEAD 128
#define CEMB 64
#define BATCH 8
#define TLEN 4096
#define BT (BATCH * TLEN)

#define BM 128
#define BN 64
#define PITCHB 272
#define NITEMS 256          // 32 q-tiles x 8 batches

// ---------------- global scratch (static) ------------------------------------
__device__ __nv_bfloat16 g_qh[(size_t)BT * HEAD];
__device__ __nv_bfloat16 g_ql[(size_t)BT * HEAD];
__device__ __nv_bfloat16 g_kh[(size_t)BT * HEAD];
__device__ __nv_bfloat16 g_kl[(size_t)BT * HEAD];
__device__ __half        g_vh[(size_t)BT * HEAD];
__device__ __half        g_vl[(size_t)BT * HEAD];
__device__ unsigned int  g_ctr;

extern __shared__ char smem_raw[];

// ---------------- helpers ----------------------------------------------------
__device__ __forceinline__ uint32_t su32(const void* p) {
    uint32_t a;
    asm("{ .reg .u64 t; cvta.to.shared.u64 t, %1; cvt.u32.u64 %0, t; }"
        : "=r"(a) : "l"(p));
    return a;
}

__device__ __forceinline__ void mma_bf16(float* c, const uint32_t* a, const uint32_t* b) {
    asm volatile(
        "mma.sync.aligned.m16n8k16.row.col.f32.bf16.bf16.f32 "
        "{%0,%1,%2,%3}, {%4,%5,%6,%7}, {%8,%9}, {%0,%1,%2,%3};"
        : "+f"(c[0]), "+f"(c[1]), "+f"(c[2]), "+f"(c[3])
        : "r"(a[0]), "r"(a[1]), "r"(a[2]), "r"(a[3]), "r"(b[0]), "r"(b[1]));
}
__device__ __forceinline__ void mma_f16(float* c, const uint32_t* a, const uint32_t* b) {
    asm volatile(
        "mma.sync.aligned.m16n8k16.row.col.f32.f16.f16.f32 "
        "{%0,%1,%2,%3}, {%4,%5,%6,%7}, {%8,%9}, {%0,%1,%2,%3};"
        : "+f"(c[0]), "+f"(c[1]), "+f"(c[2]), "+f"(c[3])
        : "r"(a[0]), "r"(a[1]), "r"(a[2]), "r"(a[3]), "r"(b[0]), "r"(b[1]));
}

__device__ __forceinline__ void ldsm4(uint32_t* r, uint32_t addr) {
    asm volatile("ldmatrix.sync.aligned.m8n8.x4.shared.b16 {%0,%1,%2,%3}, [%4];"
                 : "=r"(r[0]), "=r"(r[1]), "=r"(r[2]), "=r"(r[3]) : "r"(addr));
}
__device__ __forceinline__ void ldsm4t(uint32_t* r, uint32_t addr) {
    asm volatile("ldmatrix.sync.aligned.m8n8.x4.trans.shared.b16 {%0,%1,%2,%3}, [%4];"
                 : "=r"(r[0]), "=r"(r[1]), "=r"(r[2]), "=r"(r[3]) : "r"(addr));
}

__device__ __forceinline__ uint32_t pack2(__nv_bfloat16 a, __nv_bfloat16 b) {
    __nv_bfloat162 t = __halves2bfloat162(a, b);
    return *reinterpret_cast<uint32_t*>(&t);
}
__device__ __forceinline__ uint32_t pack2h(__half a, __half b) {
    __half2 t = __halves2half2(a, b);
    return *reinterpret_cast<uint32_t*>(&t);
}

__device__ __forceinline__ float fexp2(float x) {
    float y;
    asm("ex2.approx.ftz.f32 %0, %1;" : "=f"(y) : "f"(x));
    return y;
}

#define CP_ASYNC16(dst, src) \
    asm volatile("cp.async.cg.shared.global [%0], [%1], 16;" :: "r"(dst), "l"(src))
#define CP_COMMIT() asm volatile("cp.async.commit_group;" ::: "memory")
#define CP_WAIT(n)  asm volatile("cp.async.wait_group %0;" :: "n"(n) : "memory")

__device__ __forceinline__ void split2(float v0, float v1, uint32_t& hi, uint32_t& lo) {
    __nv_bfloat16 h0 = __float2bfloat16(v0);
    __nv_bfloat16 h1 = __float2bfloat16(v1);
    hi = pack2(h0, h1);
    lo = pack2(__float2bfloat16(v0 - __bfloat162float(h0)),
               __float2bfloat16(v1 - __bfloat162float(h1)));
}
__device__ __forceinline__ void split2h(float v0, float v1, uint32_t& hi, uint32_t& lo) {
    __half h0 = __float2half_rn(v0);
    __half h1 = __float2half_rn(v1);
    hi = pack2h(h0, h1);
    lo = pack2h(__float2half_rn(v0 - __half2float(h0)),
                __float2half_rn(v1 - __half2float(h1)));
}

// ---------------------------------------------------------------------------
// Kernel 0: reset work counter (graph-capturable)
// ---------------------------------------------------------------------------
__global__ void reset_kernel() { g_ctr = 0u; }

// ---------------------------------------------------------------------------
// Kernel 1: QKV projection on tensor cores (3-term split-bf16 math).
// Q/K written as bf16 hi/lo (log2e folded into Wq); V as fp16 hi/lo.
// ---------------------------------------------------------------------------
#define XPITCH 144
#define WPITCH 784
#define P_XH 0
#define P_XL (128 * XPITCH)
#define P_WH (2 * 128 * XPITCH)
#define P_WL (P_WH + 64 * WPITCH)
#define PROJ_SMEM (P_WL + 64 * WPITCH)

__global__ __launch_bounds__(256) void proj_kernel(
    const float* __restrict__ x,
    const float* __restrict__ Wq,
    const float* __restrict__ Wk,
    const float* __restrict__ Wv)
{
    char* sm = smem_raw;
    const uint32_t sb = su32(sm);
    const int tid  = threadIdx.x;
    const int wid  = tid >> 5;
    const int lane = tid & 31;
    const int gid  = lane >> 2;
    const int tig  = lane & 3;
    const int row0 = blockIdx.x * 128;
    const float qsc = rsqrtf((float)HEAD) * 1.4426950408889634f;

    #pragma unroll
    for (int ii = 0; ii < 8; ii++) {
        int i = tid + ii * 256;
        int r = i >> 4, c4 = i & 15;
        float4 v = ((const float4*)(x + (size_t)(row0 + r) * CEMB))[c4];
        uint32_t h0, l0, h1, l1;
        split2(v.x, v.y, h0, l0);
        split2(v.z, v.w, h1, l1);
        char* d = sm + P_XH + r * XPITCH + c4 * 8;
        *(uint32_t*)d = h0; *(uint32_t*)(d + 4) = h1;
        char* d2 = sm + P_XL + r * XPITCH + c4 * 8;
        *(uint32_t*)d2 = l0; *(uint32_t*)(d2 + 4) = l1;
    }
    #pragma unroll
    for (int ii = 0; ii < 24; ii++) {
        int i = tid + ii * 256;
        int r = i / 96, c4 = i % 96;
        int col = 4 * c4, a = col >> 7, lcol = col & 127;
        const float* ws = (a == 0 ? Wq : (a == 1 ? Wk : Wv)) + r * 128 + lcol;
        float4 v = *(const float4*)ws;
        if (a == 0) { v.x *= qsc; v.y *= qsc; v.z *= qsc; v.w *= qsc; }
        uint32_t h0, l0, h1, l1;
        split2(v.x, v.y, h0, l0);
        split2(v.z, v.w, h1, l1);
        char* d = sm + P_WH + r * WPITCH + col * 2;
        *(uint32_t*)d = h0; *(uint32_t*)(d + 4) = h1;
        char* d2 = sm + P_WL + r * WPITCH + col * 2;
        *(uint32_t*)d2 = l0; *(uint32_t*)(d2 + 4) = l1;
    }
    __syncthreads();

    const int wr0 = wid * 16;
    uint32_t axh[4][4], axl[4][4];
    {
        const int arow = (lane & 7) + ((lane >> 3) & 1) * 8;
        const int acol = (lane >> 4) * 8;
        #pragma unroll
        for (int ks = 0; ks < 4; ks++) {
            uint32_t ad = sb + P_XH + (wr0 + arow) * XPITCH + (ks * 16 + acol) * 2;
            ldsm4(axh[ks], ad);
            ldsm4(axl[ks], ad + (P_XL - P_XH));
        }
    }

    #pragma unroll
    for (int chunk = 0; chunk < 6; chunk++) {
        float c[8][4];
        #pragma unroll
        for (int i = 0; i < 8; i++)
            #pragma unroll
            for (int j = 0; j < 4; j++) c[i][j] = 0.f;

        #pragma unroll
        for (int ks = 0; ks < 4; ks++) {
            #pragma unroll
            for (int q = 0; q < 4; q++) {
                uint32_t wh[4], wl[4];
                const int i7 = lane & 7, sel = lane >> 3;
                uint32_t off = (uint32_t)((ks * 16 + i7 + ((sel & 1) << 3)) * WPITCH +
                                          (chunk * 64 + q * 16 + ((sel >> 1) << 3)) * 2);
                ldsm4t(wh, sb + P_WH + off);
                ldsm4t(wl, sb + P_WL + off);
                #pragma unroll
                for (int term = 0; term < 3; term++) {
                    const uint32_t* a = (term == 2) ? axl[ks] : axh[ks];
                    const uint32_t* bb = (term == 1) ? wl : wh;
                    mma_bf16(c[2 * q],     a, &bb[0]);
                    mma_bf16(c[2 * q + 1], a, &bb[2]);
                }
            }
        }

        const size_t rb = (size_t)(row0 + wr0 + gid) * HEAD;
        if (chunk < 4) {
            __nv_bfloat16* dh = (chunk < 2) ? g_qh : g_kh;
            __nv_bfloat16* dl = (chunk < 2) ? g_ql : g_kl;
            const int colbase = (chunk & 1) * 64;
            #pragma unroll
            for (int nb = 0; nb < 8; nb++) {
                const int col = colbase + 8 * nb + 2 * tig;
                uint32_t h, l;
                split2(c[nb][0], c[nb][1], h, l);
                *(uint32_t*)(dh + rb + col) = h;
                *(uint32_t*)(dl + rb + col) = l;
                split2(c[nb][2], c[nb][3], h, l);
                *(uint32_t*)(dh + rb + 8 * HEAD + col) = h;
                *(uint32_t*)(dl + rb + 8 * HEAD + col) = l;
            }
        } else {
            const int colbase = (chunk - 4) * 64;
            #pragma unroll
            for (int nb = 0; nb < 8; nb++) {
                const int col = colbase + 8 * nb + 2 * tig;
                uint32_t h, l;
                split2h(c[nb][0], c[nb][1], h, l);
                *(uint32_t*)(g_vh + rb + col) = h;
                *(uint32_t*)(g_vl + rb + col) = l;
                split2h(c[nb][2], c[nb][3], h, l);
                *(uint32_t*)(g_vh + rb + 8 * HEAD + col) = h;
                *(uint32_t*)(g_vl + rb + 8 * HEAD + col) = l;
            }
        }
    }
}

// ---------------------------------------------------------------------------
// Kernel 2: persistent flash attention; QK bf16 3-term, PV fp16 2-term;
// cross-tile interleave of QK(t+1) with PV(t); 3-slot cp.async ring.
// ---------------------------------------------------------------------------
#define BUFB (4 * 64 * PITCHB)
#define NBUF 3
#define ATTN_SMEM (NBUF * BUFB)

__global__ __launch_bounds__(256, 1) void attn_kernel(float* __restrict__ out)
{
    char* sm = smem_raw;
    const uint32_t sb = su32(sm);
    __shared__ unsigned int s_item;
    const int tid  = threadIdx.x;
    const int wid  = tid >> 5;
    const int lane = tid & 31;
    const int gid  = lane >> 2;
    const int tig  = lane & 3;

    while (true) {
        if (tid == 0) s_item = atomicAdd(&g_ctr, 1u);
        __syncthreads();
        const unsigned int item = s_item;
        if (item >= NITEMS) break;

        const int qx = 31 - (int)(item >> 3);   // heavy tiles first
        const int b  = (int)(item & 7);
        const int q0 = qx * BM;
        const int grow0 = q0 + wid * 16 + gid;
        const int wrow_max = q0 + wid * 16 + 15;
        const int ntile = 2 * qx + 2;

        const __nv_bfloat16* kh_g = g_kh + (size_t)b * TLEN * HEAD;
        const __nv_bfloat16* kl_g = g_kl + (size_t)b * TLEN * HEAD;
        const __half*        vh_g = g_vh + (size_t)b * TLEN * HEAD;
        const __half*        vl_g = g_vl + (size_t)b * TLEN * HEAD;

        auto stage = [&](int buf, int t) {
            const int k0 = t * BN;
            const uint32_t d0 = sb + buf * BUFB;
            #pragma unroll
            for (int ii = 0; ii < 8; ii++) {         // K hi+lo
                int i = tid + ii * 256;
                int sub = i >> 10, j = i & 1023, r = j >> 4, c = j & 15;
                const __nv_bfloat16* s0 = (sub == 0 ? kh_g : kl_g) + (size_t)(k0 + r) * HEAD + c * 8;
                CP_ASYNC16(d0 + sub * 64 * PITCHB + r * PITCHB + c * 16, (const void*)s0);
            }
            #pragma unroll
            for (int ii = 0; ii < 8; ii++) {         // V hi+lo
                int i = tid + ii * 256;
                int sub = i >> 10, j = i & 1023, r = j >> 4, c = j & 15;
                const __half* s0 = (sub == 0 ? vh_g : vl_g) + (size_t)(k0 + r) * HEAD + c * 8;
                CP_ASYNC16(d0 + (2 + sub) * 64 * PITCHB + r * PITCHB + c * 16, (const void*)s0);
            }
            CP_COMMIT();
        };

        // ---- ring prologue ----
        stage(0, 0);
        stage(1, 1);

        // ---- Q fragments ----
        uint32_t aqh[8][4], aql[8][4];
        {
            const size_t rb = (size_t)b * TLEN + grow0;
            #pragma unroll
            for (int kc = 0; kc < 8; kc++) {
                const int col = kc * 16 + 2 * tig;
                aqh[kc][0] = *(const uint32_t*)(g_qh + rb * HEAD + col);
                aqh[kc][1] = *(const uint32_t*)(g_qh + (rb + 8) * HEAD + col);
                aqh[kc][2] = *(const uint32_t*)(g_qh + rb * HEAD + col + 8);
                aqh[kc][3] = *(const uint32_t*)(g_qh + (rb + 8) * HEAD + col + 8);
                aql[kc][0] = *(const uint32_t*)(g_ql + rb * HEAD + col);
                aql[kc][1] = *(const uint32_t*)(g_ql + (rb + 8) * HEAD + col);
                aql[kc][2] = *(const uint32_t*)(g_ql + rb * HEAD + col + 8);
                aql[kc][3] = *(const uint32_t*)(g_ql + (rb + 8) * HEAD + col + 8);
            }
        }

        float o[16][4];
        #pragma unroll
        for (int i = 0; i < 16; i++)
            #pragma unroll
            for (int j = 0; j < 4; j++) o[i][j] = 0.f;
        float m0 = -3.0e38f, m1 = -3.0e38f, l0 = 0.f, l1 = 0.f;
        uint32_t pfa[8], pfb[8];        // P(t) fp16 fragments

        for (int t = -1; t < ntile; t++) {
            CP_WAIT(0);
            __syncthreads();
            if (t >= 0 && t + 2 < ntile) stage((t + 2) % NBUF, t + 2);

            const bool qkA = (t + 1 < ntile) && (BN * (t + 1) <= wrow_max);
            const bool pvA = (t >= 0) && (BN * t <= wrow_max);
            const uint32_t KH = sb + ((t + 1) % NBUF) * BUFB;
            const uint32_t KL = KH + 64 * PITCHB;
            const uint32_t VH = sb + ((t + NBUF) % NBUF) * BUFB + 2 * 64 * PITCHB;
            const uint32_t VL = VH + 64 * PITCHB;

            float s[8][4];
            #pragma unroll
            for (int i = 0; i < 8; i++)
                #pragma unroll
                for (int j = 0; j < 4; j++) s[i][j] = 0.f;

            // ---- interleaved: QK(t+1) chunks + PV(t) chunks ----
            #pragma unroll
            for (int kc = 0; kc < 8; kc++) {
                if (qkA) {
                    #pragma unroll
                    for (int pp = 0; pp < 2; pp++) {
                        uint32_t kh[2][4], kl[2][4];
                        #pragma unroll
                        for (int u = 0; u < 2; u++) {
                            const int p = 2 * pp + u;
                            const int i7 = lane & 7, sel = lane >> 3;
                            const uint32_t off =
                                (uint32_t)((16 * p + i7 + ((sel >> 1) << 3)) * PITCHB +
                                           (kc * 16 + ((sel & 1) << 3)) * 2);
                            ldsm4(kh[u], KH + off);
                            ldsm4(kl[u], KL + off);
                        }
                        #pragma unroll
                        for (int term = 0; term < 3; term++) {
                            const uint32_t* a = (term == 2) ? aql[kc] : aqh[kc];
                            const uint32_t (*bb)[4] = (term == 1) ? kl : kh;
                            mma_bf16(s[4 * pp + 0], a, &bb[0][0]);
                            mma_bf16(s[4 * pp + 1], a, &bb[0][2]);
                            mma_bf16(s[4 * pp + 2], a, &bb[1][0]);
                            mma_bf16(s[4 * pp + 3], a, &bb[1][2]);
                        }
                    }
                }
                if ((kc & 1) && pvA) {
                    const int c = kc >> 1;
                    const uint32_t ah[4] = { pfa[2 * c], pfb[2 * c], pfa[2 * c + 1], pfb[2 * c + 1] };
                    #pragma unroll
                    for (int qq = 0; qq < 4; qq++) {
                        uint32_t vh[2][4], vl[2][4];
                        #pragma unroll
                        for (int u = 0; u < 2; u++) {
                            const int q = 2 * qq + u;
                            const int i7 = lane & 7, sel = lane >> 3;
                            const uint32_t off =
                                (uint32_t)((c * 16 + i7 + ((sel & 1) << 3)) * PITCHB +
                                           (16 * q + ((sel >> 1) << 3)) * 2);
                            ldsm4t(vh[u], VH + off);
                            ldsm4t(vl[u], VL + off);
                        }
                        mma_f16(o[4 * qq + 0], ah, &vh[0][0]);
                        mma_f16(o[4 * qq + 1], ah, &vh[0][2]);
                        mma_f16(o[4 * qq + 2], ah, &vh[1][0]);
                        mma_f16(o[4 * qq + 3], ah, &vh[1][2]);
                        mma_f16(o[4 * qq + 0], ah, &vl[0][0]);
                        mma_f16(o[4 * qq + 1], ah, &vl[0][2]);
                        mma_f16(o[4 * qq + 2], ah, &vl[1][0]);
                        mma_f16(o[4 * qq + 3], ah, &vl[1][2]);
                    }
                }
            }

            // ---- softmax(t+1): mask, online max/sum, P fp16, O rescale ----
            if (qkA) {
                const int k0n = BN * (t + 1);
                if (k0n + 63 > grow0) {
                    #pragma unroll
                    for (int nb = 0; nb < 8; nb++) {
                        #pragma unroll
                        for (int j = 0; j < 2; j++) {
                            const int c = k0n + 8 * nb + 2 * tig + j;
                            if (c > grow0)     s[nb][j]     = -3.0e38f;
                            if (c > grow0 + 8) s[nb][2 + j] = -3.0e38f;
                        }
                    }
                }
                float mx0 = m0, mx1 = m1;
                #pragma unroll
                for (int nb = 0; nb < 8; nb++) {
                    mx0 = fmaxf(mx0, fmaxf(s[nb][0], s[nb][1]));
                    mx1 = fmaxf(mx1, fmaxf(s[nb][2], s[nb][3]));
                }
                mx0 = fmaxf(mx0, __shfl_xor_sync(0xffffffffu, mx0, 1));
                mx0 = fmaxf(mx0, __shfl_xor_sync(0xffffffffu, mx0, 2));
                mx1 = fmaxf(mx1, __shfl_xor_sync(0xffffffffu, mx1, 1));
                mx1 = fmaxf(mx1, __shfl_xor_sync(0xffffffffu, mx1, 2));
                const float sf0 = fexp2(m0 - mx0);
                const float sf1 = fexp2(m1 - mx1);
                float sum0 = 0.f, sum1 = 0.f;
                #pragma unroll
                for (int nb = 0; nb < 8; nb++) {
                    // round to fp16 first; sum the ROUNDED values for num/den consistency
                    __half p0 = __float2half_rn(fexp2(s[nb][0] - mx0));
                    __half p1 = __float2half_rn(fexp2(s[nb][1] - mx0));
                    __half p2 = __float2half_rn(fexp2(s[nb][2] - mx1));
                    __half p3 = __float2half_rn(fexp2(s[nb][3] - mx1));
                    pfa[nb] = pack2h(p0, p1);
                    pfb[nb] = pack2h(p2, p3);
                    sum0 += __half2float(p0) + __half2float(p1);
                    sum1 += __half2float(p2) + __half2float(p3);
                }
                sum0 += __shfl_xor_sync(0xffffffffu, sum0, 1);
                sum0 += __shfl_xor_sync(0xffffffffu, sum0, 2);
                sum1 += __shfl_xor_sync(0xffffffffu, sum1, 1);
                sum1 += __shfl_xor_sync(0xffffffffu, sum1, 2);
                l0 = l0 * sf0 + sum0;  l1 = l1 * sf1 + sum1;
                m0 = mx0;  m1 = mx1;
                #pragma unroll
                for (int nb = 0; nb < 16; nb++) {
                    o[nb][0] *= sf0; o[nb][1] *= sf0;
                    o[nb][2] *= sf1; o[nb][3] *= sf1;
                }
            }
        }

        // ---- epilogue ----
        const float inv0 = 1.f / l0;
        const float inv1 = 1.f / l1;
        float* og = out + ((size_t)b * TLEN + grow0) * HEAD;
        #pragma unroll
        for (int nb = 0; nb < 16; nb++) {
            const int col = 8 * nb + 2 * tig;
            *(float2*)(og + col)            = make_float2(o[nb][0] * inv0, o[nb][1] * inv0);
            *(float2*)(og + 8 * HEAD + col) = make_float2(o[nb][2] * inv1, o[nb][3] * inv1);
        }
    }
}

// ---------------------------------------------------------------------------
extern "C" void kernel_launch(void* const* d_in, const int* in_sizes, int n_in,
                              void* d_out, int out_size)
{
    (void)in_sizes; (void)n_in; (void)out_size;
    const float* x  = (const float*)d_in[0];
    const float* Wq = (const float*)d_in[1];
    const float* Wk = (const float*)d_in[2];
    const float* Wv = (const float*)d_in[3];
    float* out = (float*)d_out;

    static int nsm = -1;
    if (nsm < 0) {
        if (cudaDeviceGetAttribute(&nsm, cudaDevAttrMultiProcessorCount, 0) != cudaSuccess
            || nsm <= 0) nsm = 148;
    }

    static bool attr_done = false;
    if (!attr_done) {
        cudaFuncSetAttribute(proj_kernel, cudaFuncAttributeMaxDynamicSharedMemorySize,
                             (int)PROJ_SMEM);
        cudaFuncSetAttribute(attn_kernel, cudaFuncAttributeMaxDynamicSharedMemorySize,
                             (int)ATTN_SMEM);
        attr_done = true;
    }

    reset_kernel<<<1, 1>>>();
    proj_kernel<<<BT / 128, 256, PROJ_SMEM>>>(x, Wq, Wk, Wv);
    attn_kernel<<<nsm, 256, ATTN_SMEM>>>(out);
}